// round 7
// baseline (speedup 1.0000x reference)
#include <cuda_runtime.h>
#include <cstdint>

// BilinearInteraction: out[b, p, :] = x[b, i_p, :] * (x[b, j_p, :] @ W)
//   x: [4096, 32, 64] f32, W: [64, 64] f32, out: [4096, 496, 64] f32
//   R6 frame tuned for 7 CTAs/SM (grid 4096 -> 3.95 waves, tail ~1%):
//   - smem 32,264 B: swizzled xs (8 KB), vs as 31 rows (vid[0] unused),
//     W as 63 smem rows + row 63 folded into acc init via hot LDG
//   - GEMM: 1 row x 2 e-cols per thread (low reg pressure, fits 36 regs)
//   - W via cp.async.bulk; row-sequential store streams

#define NF 32
#define ED 64
#define NP 496
#define NTHREADS 256
#define NBATCH 4096

__device__ __forceinline__ unsigned smem_u32(const void* p) {
    unsigned a;
    asm("{ .reg .u64 t; cvta.to.shared.u64 t, %1; cvt.u32.u64 %0, t; }"
        : "=r"(a) : "l"(p));
    return a;
}

__global__ void __launch_bounds__(NTHREADS, 7)
bilinear_kernel(const float* __restrict__ x,
                const float* __restrict__ W,
                float* __restrict__ out)
{
    __shared__ float4 xs4[NF * 16];          // 8192 B, col ^= (row&3)*4
    __shared__ float4 vs4[(NF - 1) * 16];    // 7936 B, row j-1, col ^= ((j-1)&3)*4
    __shared__ float4 Ws4[63 * 16];          // 16128 B, W rows 0..62
    __shared__ __align__(8) unsigned long long mbar;

    const int b   = blockIdx.x;
    const int tid = threadIdx.x;

    // ---- mbarrier init, then W rows 0..62 via 1D bulk copy ----
    if (tid == 0) {
        asm volatile("mbarrier.init.shared.b64 [%0], 1;"
                     :: "r"(smem_u32(&mbar)) : "memory");
    }
    __syncthreads();
    if (tid == 0) {
        const unsigned mb = smem_u32(&mbar);
        asm volatile("mbarrier.arrive.expect_tx.shared.b64 _, [%0], %1;"
                     :: "r"(mb), "r"(16128u) : "memory");
        asm volatile(
            "cp.async.bulk.shared::cluster.global.mbarrier::complete_tx::bytes "
            "[%0], [%1], %2, [%3];"
            :: "r"(smem_u32(Ws4)), "l"(W), "r"(16128u), "r"(mb) : "memory");
    }

    // ---- x prologue: swizzled copy (512 f4) ----
    {
        const float4* xg = (const float4*)(x + (size_t)b * (NF * ED));
#pragma unroll
        for (int k = 0; k < 2; k++) {
            const int idx = tid + k * NTHREADS;   // 0..511
            const int row = idx >> 4;
            const int col = idx & 15;
            xs4[row * 16 + (col ^ ((row & 3) * 4))] = xg[idx];
        }
    }
    __syncthreads();

    // ---- wait for W (acquire) ----
    {
        const unsigned mb = smem_u32(&mbar);
        unsigned done;
        asm volatile(
            "{\n\t.reg .pred p;\n\t"
            "mbarrier.try_wait.parity.acquire.cta.shared::cta.b64 p, [%1], 0;\n\t"
            "selp.b32 %0, 1, 0, p;\n\t}"
            : "=r"(done) : "r"(mb) : "memory");
        while (!done) {
            asm volatile(
                "{\n\t.reg .pred p;\n\t"
                "mbarrier.try_wait.parity.acquire.cta.shared::cta.b64 p, [%1], 0, 0x989680;\n\t"
                "selp.b32 %0, 1, 0, p;\n\t}"
                : "=r"(done) : "r"(mb) : "memory");
        }
    }

    // ---- GEMM: vid[f][e] = sum_d x[f][d] * W[d][e] ----
    // Thread: row f = 4*warp + (lane>>3); e-f4 cols ci and ci+8 (ci = lane&7).
    // d = 63 folded into acc init via LDG of global W row 63 (hot in L1/L2).
    {
        const int w    = tid >> 5;
        const int lane = tid & 31;
        const int fi   = lane >> 3;
        const int ci   = lane & 7;
        const int f    = 4 * w + fi;
        const int sx   = (f & 3) * 4;        // = fi*4, xs column swizzle

        const float4* Wg = (const float4*)W;

        // init: acc = x[f][63] * W[63][:]
        float4 xv  = xs4[f * 16 + (15 ^ sx)];
        float4 wv0 = Wg[63 * 16 + ci];
        float4 wv1 = Wg[63 * 16 + 8 + ci];
        float4 acc0, acc1;
        acc0.x = xv.w * wv0.x; acc0.y = xv.w * wv0.y;
        acc0.z = xv.w * wv0.z; acc0.w = xv.w * wv0.w;
        acc1.x = xv.w * wv1.x; acc1.y = xv.w * wv1.y;
        acc1.z = xv.w * wv1.z; acc1.w = xv.w * wv1.w;

#pragma unroll 5
        for (int d4 = 0; d4 < 15; d4++) {
            xv = xs4[f * 16 + (d4 ^ sx)];
#pragma unroll
            for (int dd = 0; dd < 4; dd++) {
                const int d = 4 * d4 + dd;
                wv0 = Ws4[d * 16 + ci];
                wv1 = Ws4[d * 16 + 8 + ci];
                const float xsc = (dd == 0) ? xv.x : (dd == 1) ? xv.y :
                                  (dd == 2) ? xv.z : xv.w;
                acc0.x = fmaf(xsc, wv0.x, acc0.x);
                acc0.y = fmaf(xsc, wv0.y, acc0.y);
                acc0.z = fmaf(xsc, wv0.z, acc0.z);
                acc0.w = fmaf(xsc, wv0.w, acc0.w);
                acc1.x = fmaf(xsc, wv1.x, acc1.x);
                acc1.y = fmaf(xsc, wv1.y, acc1.y);
                acc1.z = fmaf(xsc, wv1.z, acc1.z);
                acc1.w = fmaf(xsc, wv1.w, acc1.w);
            }
        }
        // d4 = 15, dd = 0..2 (d = 60..62)
        xv = xs4[f * 16 + (15 ^ sx)];
#pragma unroll
        for (int dd = 0; dd < 3; dd++) {
            const int d = 60 + dd;
            wv0 = Ws4[d * 16 + ci];
            wv1 = Ws4[d * 16 + 8 + ci];
            const float xsc = (dd == 0) ? xv.x : (dd == 1) ? xv.y : xv.z;
            acc0.x = fmaf(xsc, wv0.x, acc0.x);
            acc0.y = fmaf(xsc, wv0.y, acc0.y);
            acc0.z = fmaf(xsc, wv0.z, acc0.z);
            acc0.w = fmaf(xsc, wv0.w, acc0.w);
            acc1.x = fmaf(xsc, wv1.x, acc1.x);
            acc1.y = fmaf(xsc, wv1.y, acc1.y);
            acc1.z = fmaf(xsc, wv1.z, acc1.z);
            acc1.w = fmaf(xsc, wv1.w, acc1.w);
        }

        if (f >= 1) {                         // vid row 0 is never read
            const int sv = ((f - 1) & 3) * 4;
            vs4[(f - 1) * 16 + (ci ^ sv)]       = acc0;
            vs4[(f - 1) * 16 + ((ci + 8) ^ sv)] = acc1;
        }
    }
    __syncthreads();

    // ---- Write phase: row-sequential stores (R2/R6 structure) ----
    // Warp w owns rows {w, 30-w, 15-w, 15+w} (warp 0: {0, 30, 15}).
    {
        const int w    = tid >> 5;
        const int lane = tid & 31;
        const int v    = lane & 15;
        const int h    = lane >> 4;

        float4* out4 = (float4*)(out + (size_t)b * (NP * ED));

        int rows[4];
        int nrows;
        if (w == 0) {
            rows[0] = 0; rows[1] = 30; rows[2] = 15; rows[3] = 0;
            nrows = 3;
        } else {
            rows[0] = w; rows[1] = 30 - w; rows[2] = 15 - w; rows[3] = 15 + w;
            nrows = 4;
        }

#pragma unroll
        for (int r = 0; r < 4; r++) {
            if (r >= nrows) break;
            const int i = rows[r];
            const float4 a  = xs4[i * 16 + (v ^ ((i & 3) * 4))];
            const int cnt   = 31 - i;
            const int iters = (cnt + 1) >> 1;
            const int p0    = (i * (63 - i)) >> 1;

#pragma unroll 2
            for (int t = 0; t < iters; t++) {
                const int j = i + 1 + 2 * t + h;
                if (j < NF) {
                    const float4 cvv =
                        vs4[(j - 1) * 16 + (v ^ (((j - 1) & 3) * 4))];
                    const int p = p0 + (j - i - 1);
                    float4 rr;
                    rr.x = a.x * cvv.x;
                    rr.y = a.y * cvv.y;
                    rr.z = a.z * cvv.z;
                    rr.w = a.w * cvv.w;
                    out4[p * 16 + v] = rr;
                }
            }
        }
    }
}

extern "C" void kernel_launch(void* const* d_in, const int* in_sizes, int n_in,
                              void* d_out, int out_size)
{
    const float* x = (const float*)d_in[0];
    const float* W = (const float*)d_in[1];
    float*       o = (float*)d_out;
    bilinear_kernel<<<NBATCH, NTHREADS>>>(x, W, o);
}

// round 8
// speedup vs baseline: 1.1089x; 1.1089x over previous
#include <cuda_runtime.h>
#include <cstdint>

// BilinearInteraction: out[b, p, :] = x[b, i_p, :] * (x[b, j_p, :] @ W)
//   x: [4096, 32, 64] f32, W: [64, 64] f32, out: [4096, 496, 64] f32
//   R6 compute frame + TMA bulk STORES: products staged in per-warp smem
//   double buffers (STS.128), drained by cp.async.bulk (no STG issue cost).

#define NF 32
#define ED 64
#define NP 496
#define NTHREADS 256
#define NBATCH 4096

// Dynamic smem layout (float4 units)
#define XS_OFF 0                   // 32 rows * 17 f4 (padded)  = 544
#define XSTR   17
#define VS_OFF 544                 // 32 rows * 16 f4           = 512
#define WS_OFF 1056                // 64 rows * 16 f4           = 1024
#define BUF_OFF 2080               // 8 warps * 2 * 128 f4      = 2048
#define MBAR_OFF 4128              // 1 f4 slot for mbarrier
#define SMEM_BYTES ((MBAR_OFF + 1) * 16)   // 66064 B -> 3 CTAs/SM

__device__ __forceinline__ unsigned smem_u32(const void* p) {
    unsigned a;
    asm("{ .reg .u64 t; cvta.to.shared.u64 t, %1; cvt.u32.u64 %0, t; }"
        : "=r"(a) : "l"(p));
    return a;
}

__global__ void __launch_bounds__(NTHREADS, 3)
bilinear_kernel(const float* __restrict__ x,
                const float* __restrict__ W,
                float* __restrict__ out)
{
    extern __shared__ float4 sm4[];
    unsigned long long* mbar = (unsigned long long*)(sm4 + MBAR_OFF);

    const int b   = blockIdx.x;
    const int tid = threadIdx.x;

    // ---- mbarrier init + W via 1D bulk load (async proxy) ----
    if (tid == 0) {
        asm volatile("mbarrier.init.shared.b64 [%0], 1;"
                     :: "r"(smem_u32(mbar)) : "memory");
    }
    __syncthreads();
    if (tid == 0) {
        const unsigned mb = smem_u32(mbar);
        asm volatile("mbarrier.arrive.expect_tx.shared.b64 _, [%0], %1;"
                     :: "r"(mb), "r"(16384u) : "memory");
        asm volatile(
            "cp.async.bulk.shared::cluster.global.mbarrier::complete_tx::bytes "
            "[%0], [%1], %2, [%3];"
            :: "r"(smem_u32(sm4 + WS_OFF)), "l"(W), "r"(16384u), "r"(mb)
            : "memory");
    }

    // ---- x prologue: padded copy ----
    {
        const float4* xg = (const float4*)(x + (size_t)b * (NF * ED));
#pragma unroll
        for (int k = 0; k < 2; k++) {
            const int idx = tid + k * NTHREADS;   // 0..511
            const int row = idx >> 4;
            const int col = idx & 15;
            sm4[XS_OFF + row * XSTR + col] = xg[idx];
        }
    }
    __syncthreads();

    // ---- wait for W ----
    {
        const unsigned mb = smem_u32(mbar);
        unsigned done;
        asm volatile(
            "{\n\t.reg .pred p;\n\t"
            "mbarrier.try_wait.parity.acquire.cta.shared::cta.b64 p, [%1], 0;\n\t"
            "selp.b32 %0, 1, 0, p;\n\t}"
            : "=r"(done) : "r"(mb) : "memory");
        while (!done) {
            asm volatile(
                "{\n\t.reg .pred p;\n\t"
                "mbarrier.try_wait.parity.acquire.cta.shared::cta.b64 p, [%1], 0, 0x989680;\n\t"
                "selp.b32 %0, 1, 0, p;\n\t}"
                : "=r"(done) : "r"(mb) : "memory");
        }
    }

    // ---- GEMM (R6 layout): vid[f][e] = sum_d x[f][d] * W[d][e] ----
    {
        const int w    = tid >> 5;
        const int lane = tid & 31;
        const int wr   = w & 3;
        const int half = w >> 2;
        const int fi   = lane >> 3;
        const int ci   = lane & 7;
        const int f0   = 8 * wr + fi;
        const int c    = 8 * half + ci;

        float4 acc0 = make_float4(0.f, 0.f, 0.f, 0.f);
        float4 acc1 = make_float4(0.f, 0.f, 0.f, 0.f);

#pragma unroll 4
        for (int d4 = 0; d4 < 16; d4++) {
            const float4 xv0 = sm4[XS_OFF + f0 * XSTR + d4];
            const float4 xv1 = sm4[XS_OFF + (f0 + 4) * XSTR + d4];
#pragma unroll
            for (int dd = 0; dd < 4; dd++) {
                const float4 wv = sm4[WS_OFF + (4 * d4 + dd) * 16 + c];
                const float xa = (dd == 0) ? xv0.x : (dd == 1) ? xv0.y :
                                 (dd == 2) ? xv0.z : xv0.w;
                const float xb = (dd == 0) ? xv1.x : (dd == 1) ? xv1.y :
                                 (dd == 2) ? xv1.z : xv1.w;
                acc0.x = fmaf(xa, wv.x, acc0.x);
                acc0.y = fmaf(xa, wv.y, acc0.y);
                acc0.z = fmaf(xa, wv.z, acc0.z);
                acc0.w = fmaf(xa, wv.w, acc0.w);
                acc1.x = fmaf(xb, wv.x, acc1.x);
                acc1.y = fmaf(xb, wv.y, acc1.y);
                acc1.z = fmaf(xb, wv.z, acc1.z);
                acc1.w = fmaf(xb, wv.w, acc1.w);
            }
        }
        sm4[VS_OFF + f0 * 16 + c]       = acc0;
        sm4[VS_OFF + (f0 + 4) * 16 + c] = acc1;
    }
    __syncthreads();

    // ---- Write phase: rows {w, 30-w, 15-w, 15+w}; 8-pair sub-tiles staged
    //      in per-warp double buffers, drained via cp.async.bulk ----
    {
        const int w    = tid >> 5;
        const int lane = tid & 31;
        const int v    = lane & 15;
        const int h    = lane >> 4;

        float4* out4 = (float4*)(out + (size_t)b * (NP * ED));
        float4* bufw = sm4 + BUF_OFF + w * 256;   // 2 x 128 f4

        int rows[4];
        int nrows;
        if (w == 0) {
            rows[0] = 0; rows[1] = 30; rows[2] = 15; rows[3] = 0;
            nrows = 3;
        } else {
            rows[0] = w; rows[1] = 30 - w; rows[2] = 15 - w; rows[3] = 15 + w;
            nrows = 4;
        }

        int parity = 0;
        int issued = 0;

#pragma unroll
        for (int r = 0; r < 4; r++) {
            if (r >= nrows) break;
            const int i = rows[r];
            const float4 a = sm4[XS_OFF + i * XSTR + v];
            const int cnt  = 31 - i;
            const int p0   = (i * (63 - i)) >> 1;

            int done = 0;
            while (done < cnt) {
                const int take = (cnt - done < 8) ? (cnt - done) : 8;
                float4* bb = bufw + parity * 128;

                // buffer reuse guard: keep <= 1 group outstanding
                if (issued >= 2) {
                    if (lane == 0)
                        asm volatile("cp.async.bulk.wait_group 1;" ::: "memory");
                }
                __syncwarp();

#pragma unroll
                for (int t = 0; t < 4; t++) {
                    const int q = 2 * t + h;          // pair idx in sub-tile
                    if (q < take) {
                        const int j = i + 1 + done + q;
                        const float4 cv = sm4[VS_OFF + j * 16 + v];
                        float4 rr;
                        rr.x = a.x * cv.x;
                        rr.y = a.y * cv.y;
                        rr.z = a.z * cv.z;
                        rr.w = a.w * cv.w;
                        bb[q * 16 + v] = rr;
                    }
                }
                __syncwarp();

                if (lane == 0) {
                    asm volatile("fence.proxy.async.shared::cta;" ::: "memory");
                    asm volatile(
                        "cp.async.bulk.global.shared::cta.bulk_group "
                        "[%0], [%1], %2;"
                        :: "l"(out4 + (p0 + done) * 16),
                           "r"(smem_u32(bb)),
                           "r"((unsigned)(take * 256))
                        : "memory");
                    asm volatile("cp.async.bulk.commit_group;" ::: "memory");
                }
                issued++;
                parity ^= 1;
                done += take;
            }
        }

        // drain all outstanding stores before exit
        if (lane == 0)
            asm volatile("cp.async.bulk.wait_group 0;" ::: "memory");
        __syncwarp();
    }
}

extern "C" void kernel_launch(void* const* d_in, const int* in_sizes, int n_in,
                              void* d_out, int out_size)
{
    const float* x = (const float*)d_in[0];
    const float* W = (const float*)d_in[1];
    float*       o = (float*)d_out;

    cudaFuncSetAttribute(bilinear_kernel,
                         cudaFuncAttributeMaxDynamicSharedMemorySize,
                         SMEM_BYTES);
    bilinear_kernel<<<NBATCH, NTHREADS, SMEM_BYTES>>>(x, W, o);
}

// round 9
// speedup vs baseline: 1.1679x; 1.0532x over previous
#include <cuda_runtime.h>
#include <cstdint>

// BilinearInteraction: out[b, p, :] = x[b, i_p, :] * (x[b, j_p, :] @ W)
//   x: [4096, 32, 64] f32, W: [64, 64] f32, out: [4096, 496, 64] f32
//   R6 frame, persistent-CTA version:
//   - grid 888 (148 SMs x 6 CTAs), each CTA loops over 4-5 batches
//   - W via cp.async.bulk ONCE per CTA
//   - streaming cache hints: ld.cs on x, st.cs on out
//   - GEMM relayout (96 L1 wf/warp), row-sequential store streams

#define NF 32
#define ED 64
#define NP 496
#define NTHREADS 256
#define NBATCH 4096
#define GRID 888
#define XSTR 17                   // xs row stride in float4

__device__ __forceinline__ unsigned smem_u32(const void* p) {
    unsigned a;
    asm("{ .reg .u64 t; cvta.to.shared.u64 t, %1; cvt.u32.u64 %0, t; }"
        : "=r"(a) : "l"(p));
    return a;
}

__global__ void __launch_bounds__(NTHREADS, 6)
bilinear_kernel(const float* __restrict__ x,
                const float* __restrict__ W,
                float* __restrict__ out)
{
    __shared__ float4 xs4[NF * XSTR];            // 8704 B (padded)
    __shared__ float4 vs4[NF * (ED / 4)];        // 8192 B
    __shared__ float4 Ws4[ED * (ED / 4)];        // 16384 B
    __shared__ __align__(8) unsigned long long mbar;

    const int tid = threadIdx.x;

    // ---- W via 1D bulk copy, once per CTA ----
    if (tid == 0) {
        asm volatile("mbarrier.init.shared.b64 [%0], 1;"
                     :: "r"(smem_u32(&mbar)) : "memory");
    }
    __syncthreads();
    if (tid == 0) {
        const unsigned mb = smem_u32(&mbar);
        asm volatile("mbarrier.arrive.expect_tx.shared.b64 _, [%0], %1;"
                     :: "r"(mb), "r"(16384u) : "memory");
        asm volatile(
            "cp.async.bulk.shared::cluster.global.mbarrier::complete_tx::bytes "
            "[%0], [%1], %2, [%3];"
            :: "r"(smem_u32(Ws4)), "l"(W), "r"(16384u), "r"(mb) : "memory");
    }

    bool w_pending = true;

    for (int b = blockIdx.x; b < NBATCH; b += GRID) {

        // ---- x prologue: padded copy, streaming loads ----
        {
            const float4* xg = (const float4*)(x + (size_t)b * (NF * ED));
#pragma unroll
            for (int k = 0; k < 2; k++) {
                const int idx = tid + k * NTHREADS;   // 0..511
                const int row = idx >> 4;
                const int col = idx & 15;
                xs4[row * XSTR + col] = __ldcs(xg + idx);
            }
        }

        // ---- first iteration: wait for W (acquire) ----
        if (w_pending) {
            const unsigned mb = smem_u32(&mbar);
            unsigned done;
            asm volatile(
                "{\n\t.reg .pred p;\n\t"
                "mbarrier.try_wait.parity.acquire.cta.shared::cta.b64 p, [%1], 0;\n\t"
                "selp.b32 %0, 1, 0, p;\n\t}"
                : "=r"(done) : "r"(mb) : "memory");
            while (!done) {
                asm volatile(
                    "{\n\t.reg .pred p;\n\t"
                    "mbarrier.try_wait.parity.acquire.cta.shared::cta.b64 p, [%1], 0, 0x989680;\n\t"
                    "selp.b32 %0, 1, 0, p;\n\t}"
                    : "=r"(done) : "r"(mb) : "memory");
            }
            w_pending = false;
        }
        __syncthreads();

        // ---- GEMM: vid[f][e] = sum_d x[f][d] * W[d][e] ----
        // Warp w: wr = w&3 (rows 8wr..8wr+7), half = w>>2 (e-f4 cols 8h..8h+7).
        // Lane: fi = lane>>3, ci = lane&7. Thread: rows f0, f0+4; col c.
        {
            const int w    = tid >> 5;
            const int lane = tid & 31;
            const int wr   = w & 3;
            const int half = w >> 2;
            const int fi   = lane >> 3;
            const int ci   = lane & 7;
            const int f0   = 8 * wr + fi;
            const int c    = 8 * half + ci;

            float4 acc0 = make_float4(0.f, 0.f, 0.f, 0.f);
            float4 acc1 = make_float4(0.f, 0.f, 0.f, 0.f);

#pragma unroll 4
            for (int d4 = 0; d4 < 16; d4++) {
                const float4 xv0 = xs4[f0 * XSTR + d4];
                const float4 xv1 = xs4[(f0 + 4) * XSTR + d4];
#pragma unroll
                for (int dd = 0; dd < 4; dd++) {
                    const float4 wv = Ws4[(4 * d4 + dd) * 16 + c];
                    const float xa = (dd == 0) ? xv0.x : (dd == 1) ? xv0.y :
                                     (dd == 2) ? xv0.z : xv0.w;
                    const float xb = (dd == 0) ? xv1.x : (dd == 1) ? xv1.y :
                                     (dd == 2) ? xv1.z : xv1.w;
                    acc0.x = fmaf(xa, wv.x, acc0.x);
                    acc0.y = fmaf(xa, wv.y, acc0.y);
                    acc0.z = fmaf(xa, wv.z, acc0.z);
                    acc0.w = fmaf(xa, wv.w, acc0.w);
                    acc1.x = fmaf(xb, wv.x, acc1.x);
                    acc1.y = fmaf(xb, wv.y, acc1.y);
                    acc1.z = fmaf(xb, wv.z, acc1.z);
                    acc1.w = fmaf(xb, wv.w, acc1.w);
                }
            }
            vs4[f0 * 16 + c]       = acc0;
            vs4[(f0 + 4) * 16 + c] = acc1;
        }
        __syncthreads();

        // ---- Write phase: row-sequential streaming stores ----
        // Warp w owns rows {w, 30-w, 15-w, 15+w} (warp 0: {0, 30, 15}).
        {
            const int w    = tid >> 5;
            const int lane = tid & 31;
            const int v    = lane & 15;
            const int h    = lane >> 4;

            float4* out4 = (float4*)(out + (size_t)b * (NP * ED));

            int rows[4];
            int nrows;
            if (w == 0) {
                rows[0] = 0; rows[1] = 30; rows[2] = 15; rows[3] = 0;
                nrows = 3;
            } else {
                rows[0] = w; rows[1] = 30 - w; rows[2] = 15 - w; rows[3] = 15 + w;
                nrows = 4;
            }

#pragma unroll
            for (int r = 0; r < 4; r++) {
                if (r >= nrows) break;
                const int i = rows[r];
                const float4 a  = xs4[i * XSTR + v];
                const int cnt   = 31 - i;
                const int iters = (cnt + 1) >> 1;
                const int p0    = (i * (63 - i)) >> 1;

#pragma unroll 2
                for (int t = 0; t < iters; t++) {
                    const int j = i + 1 + 2 * t + h;
                    if (j < NF) {
                        const float4 cvv = vs4[j * 16 + v];
                        const int p = p0 + (j - i - 1);
                        float4 rr;
                        rr.x = a.x * cvv.x;
                        rr.y = a.y * cvv.y;
                        rr.z = a.z * cvv.z;
                        rr.w = a.w * cvv.w;
                        __stcs(out4 + p * 16 + v, rr);   // streaming store
                    }
                }
            }
        }
        __syncthreads();   // protect xs/vs before next iteration overwrites
    }
}

extern "C" void kernel_launch(void* const* d_in, const int* in_sizes, int n_in,
                              void* d_out, int out_size)
{
    const float* x = (const float*)d_in[0];
    const float* W = (const float*)d_in[1];
    float*       o = (float*)d_out;
    bilinear_kernel<<<GRID, NTHREADS>>>(x, W, o);
}

// round 10
// speedup vs baseline: 1.3743x; 1.1768x over previous
#include <cuda_runtime.h>
#include <cstdint>

// BilinearInteraction: out[b, p, :] = x[b, i_p, :] * (x[b, j_p, :] @ W)
//   x: [4096, 32, 64] f32, W: [64, 64] f32, out: [4096, 496, 64] f32
//   R6 frame (best: 90.2us) + single change: st.global.cs output stores.
//   - grid 4096, 1 batch/CTA, 6 CTAs/SM, 48 warps/SM
//   - W via cp.async.bulk; padded xs; 96-wf GEMM; row-sequential stores

#define NF 32
#define ED 64
#define NP 496
#define NTHREADS 256
#define NBATCH 4096
#define XSTR 17                   // xs row stride in float4

__device__ __forceinline__ unsigned smem_u32(const void* p) {
    unsigned a;
    asm("{ .reg .u64 t; cvta.to.shared.u64 t, %1; cvt.u32.u64 %0, t; }"
        : "=r"(a) : "l"(p));
    return a;
}

__global__ void __launch_bounds__(NTHREADS, 6)
bilinear_kernel(const float* __restrict__ x,
                const float* __restrict__ W,
                float* __restrict__ out)
{
    __shared__ float4 xs4[NF * XSTR];            // 8704 B (padded)
    __shared__ float4 vs4[NF * (ED / 4)];        // 8192 B
    __shared__ float4 Ws4[ED * (ED / 4)];        // 16384 B
    __shared__ __align__(8) unsigned long long mbar;

    const int b   = blockIdx.x;
    const int tid = threadIdx.x;

    // ---- mbarrier init, then W via 1D bulk copy (async proxy) ----
    if (tid == 0) {
        asm volatile("mbarrier.init.shared.b64 [%0], 1;"
                     :: "r"(smem_u32(&mbar)) : "memory");
    }
    __syncthreads();
    if (tid == 0) {
        const unsigned mb = smem_u32(&mbar);
        asm volatile("mbarrier.arrive.expect_tx.shared.b64 _, [%0], %1;"
                     :: "r"(mb), "r"(16384u) : "memory");
        asm volatile(
            "cp.async.bulk.shared::cluster.global.mbarrier::complete_tx::bytes "
            "[%0], [%1], %2, [%3];"
            :: "r"(smem_u32(Ws4)), "l"(W), "r"(16384u), "r"(mb) : "memory");
    }

    // ---- x prologue: padded copy ----
    {
        const float4* xg = (const float4*)(x + (size_t)b * (NF * ED));
#pragma unroll
        for (int k = 0; k < 2; k++) {
            const int idx = tid + k * NTHREADS;   // 0..511
            const int row = idx >> 4;
            const int col = idx & 15;
            xs4[row * XSTR + col] = xg[idx];
        }
    }
    __syncthreads();

    // ---- wait for W (acquire) ----
    {
        const unsigned mb = smem_u32(&mbar);
        unsigned done;
        asm volatile(
            "{\n\t.reg .pred p;\n\t"
            "mbarrier.try_wait.parity.acquire.cta.shared::cta.b64 p, [%1], 0;\n\t"
            "selp.b32 %0, 1, 0, p;\n\t}"
            : "=r"(done) : "r"(mb) : "memory");
        while (!done) {
            asm volatile(
                "{\n\t.reg .pred p;\n\t"
                "mbarrier.try_wait.parity.acquire.cta.shared::cta.b64 p, [%1], 0, 0x989680;\n\t"
                "selp.b32 %0, 1, 0, p;\n\t}"
                : "=r"(done) : "r"(mb) : "memory");
        }
    }

    // ---- GEMM: vid[f][e] = sum_d x[f][d] * W[d][e] ----
    // Warp w: wr = w&3 (rows 8wr..8wr+7), half = w>>2 (e-f4 cols 8h..8h+7).
    // Lane: fi = lane>>3 (row), ci = lane&7 (col). Rows f0, f0+4; col c.
    {
        const int w    = tid >> 5;
        const int lane = tid & 31;
        const int wr   = w & 3;
        const int half = w >> 2;
        const int fi   = lane >> 3;
        const int ci   = lane & 7;
        const int f0   = 8 * wr + fi;
        const int c    = 8 * half + ci;

        float4 acc0 = make_float4(0.f, 0.f, 0.f, 0.f);
        float4 acc1 = make_float4(0.f, 0.f, 0.f, 0.f);

#pragma unroll 4
        for (int d4 = 0; d4 < 16; d4++) {
            const float4 xv0 = xs4[f0 * XSTR + d4];
            const float4 xv1 = xs4[(f0 + 4) * XSTR + d4];
#pragma unroll
            for (int dd = 0; dd < 4; dd++) {
                const float4 wv = Ws4[(4 * d4 + dd) * 16 + c];
                const float xa = (dd == 0) ? xv0.x : (dd == 1) ? xv0.y :
                                 (dd == 2) ? xv0.z : xv0.w;
                const float xb = (dd == 0) ? xv1.x : (dd == 1) ? xv1.y :
                                 (dd == 2) ? xv1.z : xv1.w;
                acc0.x = fmaf(xa, wv.x, acc0.x);
                acc0.y = fmaf(xa, wv.y, acc0.y);
                acc0.z = fmaf(xa, wv.z, acc0.z);
                acc0.w = fmaf(xa, wv.w, acc0.w);
                acc1.x = fmaf(xb, wv.x, acc1.x);
                acc1.y = fmaf(xb, wv.y, acc1.y);
                acc1.z = fmaf(xb, wv.z, acc1.z);
                acc1.w = fmaf(xb, wv.w, acc1.w);
            }
        }
        vs4[f0 * 16 + c]       = acc0;
        vs4[(f0 + 4) * 16 + c] = acc1;
    }
    __syncthreads();

    // ---- Write phase: row-sequential streaming stores ----
    // Warp w owns rows {w, 30-w, 15-w, 15+w} (warp 0: {0, 30, 15}).
    {
        const int w    = tid >> 5;
        const int lane = tid & 31;
        const int v    = lane & 15;
        const int h    = lane >> 4;

        float4* out4 = (float4*)(out + (size_t)b * (NP * ED));

        int rows[4];
        int nrows;
        if (w == 0) {
            rows[0] = 0; rows[1] = 30; rows[2] = 15; rows[3] = 0;
            nrows = 3;
        } else {
            rows[0] = w; rows[1] = 30 - w; rows[2] = 15 - w; rows[3] = 15 + w;
            nrows = 4;
        }

#pragma unroll
        for (int r = 0; r < 4; r++) {
            if (r >= nrows) break;
            const int i = rows[r];
            const float4 a  = xs4[i * XSTR + v];
            const int cnt   = 31 - i;
            // exact trip count for this half-lane: h=0 covers even offsets,
            // h=1 odd; both bounded by cnt.
            const int iters = (cnt + 1 - h) >> 1;
            const int p0    = (i * (63 - i)) >> 1;

#pragma unroll 2
            for (int t = 0; t < iters; t++) {
                const int j = i + 1 + 2 * t + h;
                const float4 cvv = vs4[j * 16 + v];
                const int p = p0 + (j - i - 1);
                float4 rr;
                rr.x = a.x * cvv.x;
                rr.y = a.y * cvv.y;
                rr.z = a.z * cvv.z;
                rr.w = a.w * cvv.w;
                __stcs(out4 + p * 16 + v, rr);   // evict-first streaming store
            }
        }
    }
}

extern "C" void kernel_launch(void* const* d_in, const int* in_sizes, int n_in,
                              void* d_out, int out_size)
{
    const float* x = (const float*)d_in[0];
    const float* W = (const float*)d_in[1];
    float*       o = (float*)d_out;
    bilinear_kernel<<<NBATCH, NTHREADS>>>(x, W, o);
}